// round 4
// baseline (speedup 1.0000x reference)
#include <cuda_runtime.h>
#include <cuda_fp16.h>
#include <math.h>
#include <stdint.h>

// Problem constants
#define S_LEN 4096
#define BATCH 4
#define DM    1024
#define MTOT  (BATCH * S_LEN)

// GEMM tiling: CTA 128x128, 512 threads (16 warps: 8 in M x 2 in N),
// warp tile 16m x 64n, K-slab 32, 3-stage cp.async pipeline.
#define KS    32
#define NSLAB (DM / KS)        // 32
#define APITCH 40              // smem row pitch in halves (+8 pad)

// Stage layout (halves): sAh[128*40] sAl sBh sBl  -> 4*5120 = 20480 halves
#define ST_AH 0
#define ST_AL 5120
#define ST_BH 10240
#define ST_BL 15360
#define ST_HALVES 20480
#define SMEM_BYTES (3 * ST_HALVES * 2)   // 122880 B

// ---------------------------------------------------------------------------
// Scratch (device globals)
// ---------------------------------------------------------------------------
__device__ __half g_x1h[(size_t)MTOT * DM];
__device__ __half g_x1l[(size_t)MTOT * DM];
__device__ __half g_x2h[(size_t)MTOT * DM];
__device__ __half g_x2l[(size_t)MTOT * DM];
__device__ __half g_w1h[(size_t)DM * DM];   // TRANSPOSED: wt[n][k]
__device__ __half g_w1l[(size_t)DM * DM];
__device__ __half g_w2h[(size_t)DM * DM];
__device__ __half g_w2l[(size_t)DM * DM];
__device__ __half g_hh[(size_t)MTOT * DM];
__device__ __half g_hl[(size_t)MTOT * DM];
__device__ __half g_ih[(size_t)MTOT * DM];
__device__ __half g_il[(size_t)MTOT * DM];

// ---------------------------------------------------------------------------
// PTX helpers
// ---------------------------------------------------------------------------
__device__ __forceinline__ uint32_t smem_u32(const void* p) {
    return (uint32_t)__cvta_generic_to_shared(p);
}
__device__ __forceinline__ void ldsm4(uint32_t addr, uint32_t& r0, uint32_t& r1,
                                      uint32_t& r2, uint32_t& r3) {
    asm volatile("ldmatrix.sync.aligned.m8n8.x4.shared.b16 {%0,%1,%2,%3}, [%4];\n"
                 : "=r"(r0), "=r"(r1), "=r"(r2), "=r"(r3) : "r"(addr));
}
__device__ __forceinline__ void mma16816(float c[4], const uint32_t a[4],
                                         const uint32_t b[2]) {
    asm volatile(
        "mma.sync.aligned.m16n8k16.row.col.f32.f16.f16.f32 "
        "{%0,%1,%2,%3}, {%4,%5,%6,%7}, {%8,%9}, {%0,%1,%2,%3};\n"
        : "+f"(c[0]), "+f"(c[1]), "+f"(c[2]), "+f"(c[3])
        : "r"(a[0]), "r"(a[1]), "r"(a[2]), "r"(a[3]), "r"(b[0]), "r"(b[1]));
}
__device__ __forceinline__ void cp16(void* sdst, const void* gsrc) {
    uint32_t s = smem_u32(sdst);
    asm volatile("cp.async.cg.shared.global [%0], [%1], 16;\n" :: "r"(s), "l"(gsrc));
}
#define CP_COMMIT() asm volatile("cp.async.commit_group;\n" ::: "memory")
#define CP_WAIT(n)  asm volatile("cp.async.wait_group %0;\n" :: "n"(n) : "memory")

// ---------------------------------------------------------------------------
// Kernel 1: split hidden and hidden+pre_emb into fp16 hi/lo
// ---------------------------------------------------------------------------
__global__ __launch_bounds__(256) void split_x_kernel(
    const float* __restrict__ hidden, const float* __restrict__ pre) {
    size_t i = ((size_t)blockIdx.x * 256 + threadIdx.x) * 4;
    float4 hv = *(const float4*)(hidden + i);
    float4 pv = *(const float4*)(pre + i);
    float x1[4] = {hv.x, hv.y, hv.z, hv.w};
    float x2[4] = {hv.x + pv.x, hv.y + pv.y, hv.z + pv.z, hv.w + pv.w};
    __half h1[4], l1[4], h2[4], l2[4];
#pragma unroll
    for (int j = 0; j < 4; j++) {
        h1[j] = __float2half_rn(x1[j]);
        l1[j] = __float2half_rn(x1[j] - __half2float(h1[j]));
        h2[j] = __float2half_rn(x2[j]);
        l2[j] = __float2half_rn(x2[j] - __half2float(h2[j]));
    }
#pragma unroll
    for (int j = 0; j < 2; j++) {
        *(__half2*)(g_x1h + i + 2 * j) = __halves2half2(h1[2 * j], h1[2 * j + 1]);
        *(__half2*)(g_x1l + i + 2 * j) = __halves2half2(l1[2 * j], l1[2 * j + 1]);
        *(__half2*)(g_x2h + i + 2 * j) = __halves2half2(h2[2 * j], h2[2 * j + 1]);
        *(__half2*)(g_x2l + i + 2 * j) = __halves2half2(l2[2 * j], l2[2 * j + 1]);
    }
}

// ---------------------------------------------------------------------------
// Kernel 2: split + TRANSPOSE weights (wt[n][k] = w[k][n], fp16 hi/lo)
// ---------------------------------------------------------------------------
__global__ __launch_bounds__(256) void split_wT_kernel(
    const float* __restrict__ w1, const float* __restrict__ w2) {
    __shared__ float t1[32][33], t2[32][33];
    const int bx = blockIdx.x * 32, by = blockIdx.y * 32;
    const int tx = threadIdx.x & 31, ty = threadIdx.x >> 5;   // 32 x 8
#pragma unroll
    for (int i = 0; i < 32; i += 8) {
        t1[ty + i][tx] = w1[(size_t)(by + ty + i) * DM + bx + tx];
        t2[ty + i][tx] = w2[(size_t)(by + ty + i) * DM + bx + tx];
    }
    __syncthreads();
#pragma unroll
    for (int i = 0; i < 32; i += 8) {
        int n = bx + ty + i, k = by + tx;
        float v1 = t1[tx][ty + i], v2 = t2[tx][ty + i];
        __half h1 = __float2half_rn(v1), h2 = __float2half_rn(v2);
        g_w1h[(size_t)n * DM + k] = h1;
        g_w1l[(size_t)n * DM + k] = __float2half_rn(v1 - __half2float(h1));
        g_w2h[(size_t)n * DM + k] = h2;
        g_w2l[(size_t)n * DM + k] = __float2half_rn(v2 - __half2float(h2));
    }
}

// ---------------------------------------------------------------------------
// Shared mainloop (macro-free inline): accumulates into acc[8][4].
// A rows bm.., B rows bn.., both K-major [row][k] with hi/lo pairs.
// ---------------------------------------------------------------------------
struct Frags { float acc[8][4]; };

__device__ __forceinline__ void mainloop(
    __half* sm, const __half* __restrict__ Ah, const __half* __restrict__ Al,
    const __half* __restrict__ Bh, const __half* __restrict__ Bl,
    int bm, int bn, int tid, int wm, int wn, int lane, float acc[8][4])
{
    auto load_slab = [&](int k0, int s) {
        __half* stg = sm + s * ST_HALVES;
        int row = tid >> 2, cg = tid & 3;
        int so = row * APITCH + cg * 8;
        size_t ga = (size_t)(bm + row) * DM + k0 + cg * 8;
        size_t gb = (size_t)(bn + row) * DM + k0 + cg * 8;
        cp16(stg + ST_AH + so, Ah + ga);
        cp16(stg + ST_AL + so, Al + ga);
        cp16(stg + ST_BH + so, Bh + gb);
        cp16(stg + ST_BL + so, Bl + gb);
        CP_COMMIT();
    };

    load_slab(0, 0);
    load_slab(KS, 1);

    for (int i = 0; i < NSLAB; i++) {
        if (i < NSLAB - 2) { CP_WAIT(1); } else { CP_WAIT(0); }
        __syncthreads();
        if (i + 2 < NSLAB) load_slab((i + 2) * KS, (i + 2) % 3);

        const __half* stg = sm + (i % 3) * ST_HALVES;
        const __half* sAh = stg + ST_AH;
        const __half* sAl = stg + ST_AL;
        const __half* sBh = stg + ST_BH;
        const __half* sBl = stg + ST_BL;
        const int g = lane >> 3;

#pragma unroll
        for (int kk = 0; kk < KS; kk += 16) {
            uint32_t ah[4], al[4];
            {
                int row = wm * 16 + (lane & 7) + (g & 1) * 8;
                int col = kk + (g >> 1) * 8;
                ldsm4(smem_u32(sAh + row * APITCH + col), ah[0], ah[1], ah[2], ah[3]);
                ldsm4(smem_u32(sAl + row * APITCH + col), al[0], al[1], al[2], al[3]);
            }
            uint32_t bh[8][2], bl[8][2];
#pragma unroll
            for (int ng = 0; ng < 4; ng++) {
                int row = wn * 64 + ng * 16 + (lane & 7) + (g & 1) * 8;
                int col = kk + (g >> 1) * 8;
                uint32_t r0, r1, r2, r3;
                ldsm4(smem_u32(sBh + row * APITCH + col), r0, r1, r2, r3);
                bh[2 * ng][0] = r0; bh[2 * ng][1] = r2;
                bh[2 * ng + 1][0] = r1; bh[2 * ng + 1][1] = r3;
                ldsm4(smem_u32(sBl + row * APITCH + col), r0, r1, r2, r3);
                bl[2 * ng][0] = r0; bl[2 * ng][1] = r2;
                bl[2 * ng + 1][0] = r1; bl[2 * ng + 1][1] = r3;
            }
#pragma unroll
            for (int ni = 0; ni < 8; ni++) mma16816(acc[ni], ah, bh[ni]);
#pragma unroll
            for (int ni = 0; ni < 8; ni++) mma16816(acc[ni], ah, bl[ni]);
#pragma unroll
            for (int ni = 0; ni < 8; ni++) mma16816(acc[ni], al, bh[ni]);
        }
    }
}

// ---------------------------------------------------------------------------
// Kernel 3: GEMM1 — H/I[16384,1024] = X @ W + bias (W pre-transposed), split out
// ---------------------------------------------------------------------------
__global__ __launch_bounds__(512, 1) void gemm1_kernel(
    const float* __restrict__ b1, const float* __restrict__ b2) {
    extern __shared__ __half sm[];
    const int tid = threadIdx.x, lane = tid & 31, warp = tid >> 5;
    const int wm = warp >> 1, wn = warp & 1;
    const int bm = blockIdx.y * 128, bn = blockIdx.x * 128;

    const __half *Ah, *Al, *Bh, *Bl;
    __half *Ch, *Cl;
    const float* bias;
    if (blockIdx.z == 0) {
        Ah = g_x1h; Al = g_x1l; Bh = g_w1h; Bl = g_w1l;
        Ch = g_hh; Cl = g_hl; bias = b1;
    } else {
        Ah = g_x2h; Al = g_x2l; Bh = g_w2h; Bl = g_w2l;
        Ch = g_ih; Cl = g_il; bias = b2;
    }

    float acc[8][4];
#pragma unroll
    for (int ni = 0; ni < 8; ni++)
#pragma unroll
        for (int j = 0; j < 4; j++) acc[ni][j] = 0.f;

    mainloop(sm, Ah, Al, Bh, Bl, bm, bn, tid, wm, wn, lane, acc);

#pragma unroll
    for (int ni = 0; ni < 8; ni++) {
        int col = bn + wn * 64 + ni * 8 + 2 * (lane & 3);
        float2 bv = *(const float2*)(bias + col);
#pragma unroll
        for (int h = 0; h < 2; h++) {
            int row = bm + wm * 16 + (lane >> 2) + h * 8;
            float v0 = acc[ni][2 * h + 0] + bv.x;
            float v1 = acc[ni][2 * h + 1] + bv.y;
            __half h0 = __float2half_rn(v0), h1 = __float2half_rn(v1);
            __half l0 = __float2half_rn(v0 - __half2float(h0));
            __half l1 = __float2half_rn(v1 - __half2float(h1));
            *(__half2*)(Ch + (size_t)row * DM + col) = __halves2half2(h0, h1);
            *(__half2*)(Cl + (size_t)row * DM + col) = __halves2half2(l0, l1);
        }
    }
}

// ---------------------------------------------------------------------------
// Kernel 4: GEMM2 — logits = H @ I^T per batch -> d_out (fp32)
// ---------------------------------------------------------------------------
__global__ __launch_bounds__(512, 1) void gemm2_kernel(float* __restrict__ out) {
    extern __shared__ __half sm[];
    const int tid = threadIdx.x, lane = tid & 31, warp = tid >> 5;
    const int wm = warp >> 1, wn = warp & 1;
    const int bq = blockIdx.y * 128, bk = blockIdx.x * 128;
    const int bat = blockIdx.z;

    const __half* Ah = g_hh + (size_t)bat * S_LEN * DM;
    const __half* Al = g_hl + (size_t)bat * S_LEN * DM;
    const __half* Bh = g_ih + (size_t)bat * S_LEN * DM;
    const __half* Bl = g_il + (size_t)bat * S_LEN * DM;

    float acc[8][4];
#pragma unroll
    for (int ni = 0; ni < 8; ni++)
#pragma unroll
        for (int j = 0; j < 4; j++) acc[ni][j] = 0.f;

    mainloop(sm, Ah, Al, Bh, Bl, bq, bk, tid, wm, wn, lane, acc);

    float* obase = out + (size_t)bat * S_LEN * S_LEN;
#pragma unroll
    for (int ni = 0; ni < 8; ni++) {
        int col = bk + wn * 64 + ni * 8 + 2 * (lane & 3);
#pragma unroll
        for (int h = 0; h < 2; h++) {
            int row = bq + wm * 16 + (lane >> 2) + h * 8;
            *(float2*)(obase + (size_t)row * S_LEN + col) =
                make_float2(acc[ni][2 * h + 0], acc[ni][2 * h + 1]);
        }
    }
}

// ---------------------------------------------------------------------------
// Kernel 5: rowwise softmax in place over d_out (16384 rows x 4096)
// ---------------------------------------------------------------------------
__global__ __launch_bounds__(256) void softmax_kernel(float* __restrict__ out) {
    __shared__ float red[8];
    const int t = threadIdx.x, lane = t & 31, warp = t >> 5;
    float* p = out + (size_t)blockIdx.x * S_LEN;

    float4 v[4];
#pragma unroll
    for (int i = 0; i < 4; i++) v[i] = *(const float4*)(p + (i * 256 + t) * 4);

    float mx = -INFINITY;
#pragma unroll
    for (int i = 0; i < 4; i++)
        mx = fmaxf(mx, fmaxf(fmaxf(v[i].x, v[i].y), fmaxf(v[i].z, v[i].w)));
#pragma unroll
    for (int o = 16; o >= 1; o >>= 1)
        mx = fmaxf(mx, __shfl_xor_sync(0xffffffffu, mx, o));
    if (lane == 0) red[warp] = mx;
    __syncthreads();
    float bmx = red[0];
#pragma unroll
    for (int w = 1; w < 8; w++) bmx = fmaxf(bmx, red[w]);
    __syncthreads();

    float sum = 0.f;
#pragma unroll
    for (int i = 0; i < 4; i++) {
        v[i].x = expf(v[i].x - bmx); sum += v[i].x;
        v[i].y = expf(v[i].y - bmx); sum += v[i].y;
        v[i].z = expf(v[i].z - bmx); sum += v[i].z;
        v[i].w = expf(v[i].w - bmx); sum += v[i].w;
    }
#pragma unroll
    for (int o = 16; o >= 1; o >>= 1)
        sum += __shfl_xor_sync(0xffffffffu, sum, o);
    if (lane == 0) red[warp] = sum;
    __syncthreads();
    float bsum = 0.f;
#pragma unroll
    for (int w = 0; w < 8; w++) bsum += red[w];

    float inv = 1.0f / bsum;
#pragma unroll
    for (int i = 0; i < 4; i++) {
        v[i].x *= inv; v[i].y *= inv; v[i].z *= inv; v[i].w *= inv;
        *(float4*)(p + (i * 256 + t) * 4) = v[i];
    }
}

// ---------------------------------------------------------------------------
// Launch
// ---------------------------------------------------------------------------
extern "C" void kernel_launch(void* const* d_in, const int* in_sizes, int n_in,
                              void* d_out, int out_size) {
    (void)in_sizes; (void)n_in; (void)out_size;
    const float* hidden = (const float*)d_in[0];
    const float* pre    = (const float*)d_in[1];
    const float* w1     = (const float*)d_in[2];
    const float* b1     = (const float*)d_in[3];
    const float* w2     = (const float*)d_in[4];
    const float* b2     = (const float*)d_in[5];
    float* out = (float*)d_out;

    cudaFuncSetAttribute(gemm1_kernel,
                         cudaFuncAttributeMaxDynamicSharedMemorySize, SMEM_BYTES);
    cudaFuncSetAttribute(gemm2_kernel,
                         cudaFuncAttributeMaxDynamicSharedMemorySize, SMEM_BYTES);

    split_x_kernel<<<(MTOT * DM) / (256 * 4), 256>>>(hidden, pre);
    split_wT_kernel<<<dim3(DM / 32, DM / 32), 256>>>(w1, w2);
    gemm1_kernel<<<dim3(DM / 128, MTOT / 128, 2), 512, SMEM_BYTES>>>(b1, b2);
    gemm2_kernel<<<dim3(S_LEN / 128, S_LEN / 128, BATCH), 512, SMEM_BYTES>>>(out);
    softmax_kernel<<<MTOT, 256>>>(out);
}

// round 5
// speedup vs baseline: 1.6580x; 1.6580x over previous
#include <cuda_runtime.h>
#include <cuda_fp16.h>
#include <math.h>
#include <stdint.h>

// Problem constants
#define S_LEN 4096
#define BATCH 4
#define DM    1024
#define MTOT  (BATCH * S_LEN)

// GEMM tiling: CTA 128x128, 256 threads (8 warps: 4 in M x 2 in N),
// warp tile 32m x 64n, K-slab 32, 2-stage cp.async, 2 CTAs/SM.
#define KS    32
#define NSLAB (DM / KS)        // 32
#define APITCH 40              // smem row pitch in halves (+8 pad)

// Stage layout (halves): sAh[128*40] sAl sBh sBl = 4*5120 = 20480 halves
#define ST_AH 0
#define ST_AL 5120
#define ST_BH 10240
#define ST_BL 15360
#define ST_HALVES 20480
#define SMEM_BYTES (2 * ST_HALVES * 2)   // 81920 B

// ---------------------------------------------------------------------------
// Scratch (device globals)
// ---------------------------------------------------------------------------
__device__ __half g_x1h[(size_t)MTOT * DM];
__device__ __half g_x1l[(size_t)MTOT * DM];
__device__ __half g_x2h[(size_t)MTOT * DM];
__device__ __half g_x2l[(size_t)MTOT * DM];
__device__ __half g_w1h[(size_t)DM * DM];   // TRANSPOSED: wt[n][k]
__device__ __half g_w1l[(size_t)DM * DM];
__device__ __half g_w2h[(size_t)DM * DM];
__device__ __half g_w2l[(size_t)DM * DM];
__device__ __half g_hh[(size_t)MTOT * DM];
__device__ __half g_hl[(size_t)MTOT * DM];
__device__ __half g_ih[(size_t)MTOT * DM];
__device__ __half g_il[(size_t)MTOT * DM];

// ---------------------------------------------------------------------------
// PTX helpers
// ---------------------------------------------------------------------------
__device__ __forceinline__ uint32_t smem_u32(const void* p) {
    return (uint32_t)__cvta_generic_to_shared(p);
}
__device__ __forceinline__ void ldsm4(uint32_t addr, uint32_t& r0, uint32_t& r1,
                                      uint32_t& r2, uint32_t& r3) {
    asm volatile("ldmatrix.sync.aligned.m8n8.x4.shared.b16 {%0,%1,%2,%3}, [%4];\n"
                 : "=r"(r0), "=r"(r1), "=r"(r2), "=r"(r3) : "r"(addr));
}
__device__ __forceinline__ void mma16816(float c[4], const uint32_t a[4],
                                         uint32_t b0, uint32_t b1) {
    asm volatile(
        "mma.sync.aligned.m16n8k16.row.col.f32.f16.f16.f32 "
        "{%0,%1,%2,%3}, {%4,%5,%6,%7}, {%8,%9}, {%0,%1,%2,%3};\n"
        : "+f"(c[0]), "+f"(c[1]), "+f"(c[2]), "+f"(c[3])
        : "r"(a[0]), "r"(a[1]), "r"(a[2]), "r"(a[3]), "r"(b0), "r"(b1));
}
__device__ __forceinline__ void cp16(void* sdst, const void* gsrc) {
    uint32_t s = smem_u32(sdst);
    asm volatile("cp.async.cg.shared.global [%0], [%1], 16;\n" :: "r"(s), "l"(gsrc));
}
#define CP_COMMIT() asm volatile("cp.async.commit_group;\n" ::: "memory")
#define CP_WAIT(n)  asm volatile("cp.async.wait_group %0;\n" :: "n"(n) : "memory")

// ---------------------------------------------------------------------------
// Kernel 1: split hidden and hidden+pre_emb into fp16 hi/lo
// ---------------------------------------------------------------------------
__global__ __launch_bounds__(256) void split_x_kernel(
    const float* __restrict__ hidden, const float* __restrict__ pre) {
    size_t i = ((size_t)blockIdx.x * 256 + threadIdx.x) * 4;
    float4 hv = *(const float4*)(hidden + i);
    float4 pv = *(const float4*)(pre + i);
    float x1[4] = {hv.x, hv.y, hv.z, hv.w};
    float x2[4] = {hv.x + pv.x, hv.y + pv.y, hv.z + pv.z, hv.w + pv.w};
    __half h1[4], l1[4], h2[4], l2[4];
#pragma unroll
    for (int j = 0; j < 4; j++) {
        h1[j] = __float2half_rn(x1[j]);
        l1[j] = __float2half_rn(x1[j] - __half2float(h1[j]));
        h2[j] = __float2half_rn(x2[j]);
        l2[j] = __float2half_rn(x2[j] - __half2float(h2[j]));
    }
#pragma unroll
    for (int j = 0; j < 2; j++) {
        *(__half2*)(g_x1h + i + 2 * j) = __halves2half2(h1[2 * j], h1[2 * j + 1]);
        *(__half2*)(g_x1l + i + 2 * j) = __halves2half2(l1[2 * j], l1[2 * j + 1]);
        *(__half2*)(g_x2h + i + 2 * j) = __halves2half2(h2[2 * j], h2[2 * j + 1]);
        *(__half2*)(g_x2l + i + 2 * j) = __halves2half2(l2[2 * j], l2[2 * j + 1]);
    }
}

// ---------------------------------------------------------------------------
// Kernel 2: split + TRANSPOSE weights (wt[n][k] = w[k][n], fp16 hi/lo)
// ---------------------------------------------------------------------------
__global__ __launch_bounds__(256) void split_wT_kernel(
    const float* __restrict__ w1, const float* __restrict__ w2) {
    __shared__ float t1[32][33], t2[32][33];
    const int bx = blockIdx.x * 32, by = blockIdx.y * 32;
    const int tx = threadIdx.x & 31, ty = threadIdx.x >> 5;   // 32 x 8
#pragma unroll
    for (int i = 0; i < 32; i += 8) {
        t1[ty + i][tx] = w1[(size_t)(by + ty + i) * DM + bx + tx];
        t2[ty + i][tx] = w2[(size_t)(by + ty + i) * DM + bx + tx];
    }
    __syncthreads();
#pragma unroll
    for (int i = 0; i < 32; i += 8) {
        int n = bx + ty + i, k = by + tx;
        float v1 = t1[tx][ty + i], v2 = t2[tx][ty + i];
        __half h1 = __float2half_rn(v1), h2 = __float2half_rn(v2);
        g_w1h[(size_t)n * DM + k] = h1;
        g_w1l[(size_t)n * DM + k] = __float2half_rn(v1 - __half2float(h1));
        g_w2h[(size_t)n * DM + k] = h2;
        g_w2l[(size_t)n * DM + k] = __float2half_rn(v2 - __half2float(h2));
    }
}

// ---------------------------------------------------------------------------
// Shared mainloop: acc[2][8][4] += split-fp16 x3 product.
// A rows bm.., B rows bn.., both K-major [row][k] hi/lo pairs.
// B fragments are loaded transiently per ng-group to cap register liveness.
// ---------------------------------------------------------------------------
__device__ __forceinline__ void mainloop(
    __half* sm, const __half* __restrict__ Ah, const __half* __restrict__ Al,
    const __half* __restrict__ Bh, const __half* __restrict__ Bl,
    int bm, int bn, int tid, int wm, int wn, int lane, float acc[2][8][4])
{
    auto load_slab = [&](int k0, int s) {
        __half* stg = sm + s * ST_HALVES;
#pragma unroll
        for (int t = 0; t < 2; t++) {
            int slot = tid + t * 256;
            int row = slot >> 2, cg = slot & 3;
            int so = row * APITCH + cg * 8;
            size_t ga = (size_t)(bm + row) * DM + k0 + cg * 8;
            size_t gb = (size_t)(bn + row) * DM + k0 + cg * 8;
            cp16(stg + ST_AH + so, Ah + ga);
            cp16(stg + ST_AL + so, Al + ga);
            cp16(stg + ST_BH + so, Bh + gb);
            cp16(stg + ST_BL + so, Bl + gb);
        }
        CP_COMMIT();
    };

    load_slab(0, 0);

    for (int i = 0; i < NSLAB; i++) {
        const int s = i & 1;
        if (i + 1 < NSLAB) { load_slab((i + 1) * KS, s ^ 1); CP_WAIT(1); }
        else               { CP_WAIT(0); }
        __syncthreads();

        const __half* stg = sm + s * ST_HALVES;
        const __half* sAh = stg + ST_AH;
        const __half* sAl = stg + ST_AL;
        const __half* sBh = stg + ST_BH;
        const __half* sBl = stg + ST_BL;
        const int g = lane >> 3;

#pragma unroll
        for (int kk = 0; kk < KS; kk += 16) {
            uint32_t ah[2][4], al[2][4];
#pragma unroll
            for (int mi = 0; mi < 2; mi++) {
                int row = wm * 32 + mi * 16 + (lane & 7) + (g & 1) * 8;
                int col = kk + (g >> 1) * 8;
                ldsm4(smem_u32(sAh + row * APITCH + col),
                      ah[mi][0], ah[mi][1], ah[mi][2], ah[mi][3]);
                ldsm4(smem_u32(sAl + row * APITCH + col),
                      al[mi][0], al[mi][1], al[mi][2], al[mi][3]);
            }
#pragma unroll
            for (int ng = 0; ng < 4; ng++) {
                int row = wn * 64 + ng * 16 + (lane & 7) + (g & 1) * 8;
                int col = kk + (g >> 1) * 8;
                uint32_t r0, r1, r2, r3;
                // hi B fragment for ni = 2ng (r0,r2) and 2ng+1 (r1,r3)
                ldsm4(smem_u32(sBh + row * APITCH + col), r0, r1, r2, r3);
#pragma unroll
                for (int mi = 0; mi < 2; mi++) {
                    mma16816(acc[mi][2 * ng],     ah[mi], r0, r2);
                    mma16816(acc[mi][2 * ng + 1], ah[mi], r1, r3);
                    mma16816(acc[mi][2 * ng],     al[mi], r0, r2);
                    mma16816(acc[mi][2 * ng + 1], al[mi], r1, r3);
                }
                // lo B fragment
                ldsm4(smem_u32(sBl + row * APITCH + col), r0, r1, r2, r3);
#pragma unroll
                for (int mi = 0; mi < 2; mi++) {
                    mma16816(acc[mi][2 * ng],     ah[mi], r0, r2);
                    mma16816(acc[mi][2 * ng + 1], ah[mi], r1, r3);
                }
            }
        }
        __syncthreads();
    }
}

// ---------------------------------------------------------------------------
// Kernel 3: GEMM1 — H/I[16384,1024] = X @ W + bias (W pre-transposed), split out
// ---------------------------------------------------------------------------
__global__ __launch_bounds__(256, 2) void gemm1_kernel(
    const float* __restrict__ b1, const float* __restrict__ b2) {
    extern __shared__ __half sm[];
    const int tid = threadIdx.x, lane = tid & 31, warp = tid >> 5;
    const int wm = warp >> 1, wn = warp & 1;
    const int bm = blockIdx.y * 128, bn = blockIdx.x * 128;

    const __half *Ah, *Al, *Bh, *Bl;
    __half *Ch, *Cl;
    const float* bias;
    if (blockIdx.z == 0) {
        Ah = g_x1h; Al = g_x1l; Bh = g_w1h; Bl = g_w1l;
        Ch = g_hh; Cl = g_hl; bias = b1;
    } else {
        Ah = g_x2h; Al = g_x2l; Bh = g_w2h; Bl = g_w2l;
        Ch = g_ih; Cl = g_il; bias = b2;
    }

    float acc[2][8][4];
#pragma unroll
    for (int mi = 0; mi < 2; mi++)
#pragma unroll
        for (int ni = 0; ni < 8; ni++)
#pragma unroll
            for (int j = 0; j < 4; j++) acc[mi][ni][j] = 0.f;

    mainloop(sm, Ah, Al, Bh, Bl, bm, bn, tid, wm, wn, lane, acc);

#pragma unroll
    for (int mi = 0; mi < 2; mi++) {
#pragma unroll
        for (int ni = 0; ni < 8; ni++) {
            int col = bn + wn * 64 + ni * 8 + 2 * (lane & 3);
            float2 bv = *(const float2*)(bias + col);
#pragma unroll
            for (int h = 0; h < 2; h++) {
                int row = bm + wm * 32 + mi * 16 + (lane >> 2) + h * 8;
                float v0 = acc[mi][ni][2 * h + 0] + bv.x;
                float v1 = acc[mi][ni][2 * h + 1] + bv.y;
                __half h0 = __float2half_rn(v0), h1 = __float2half_rn(v1);
                __half l0 = __float2half_rn(v0 - __half2float(h0));
                __half l1 = __float2half_rn(v1 - __half2float(h1));
                *(__half2*)(Ch + (size_t)row * DM + col) = __halves2half2(h0, h1);
                *(__half2*)(Cl + (size_t)row * DM + col) = __halves2half2(l0, l1);
            }
        }
    }
}

// ---------------------------------------------------------------------------
// Kernel 4: GEMM2 — logits = H @ I^T per batch -> d_out (fp32)
// ---------------------------------------------------------------------------
__global__ __launch_bounds__(256, 2) void gemm2_kernel(float* __restrict__ out) {
    extern __shared__ __half sm[];
    const int tid = threadIdx.x, lane = tid & 31, warp = tid >> 5;
    const int wm = warp >> 1, wn = warp & 1;
    const int bq = blockIdx.y * 128, bk = blockIdx.x * 128;
    const int bat = blockIdx.z;

    const __half* Ah = g_hh + (size_t)bat * S_LEN * DM;
    const __half* Al = g_hl + (size_t)bat * S_LEN * DM;
    const __half* Bh = g_ih + (size_t)bat * S_LEN * DM;
    const __half* Bl = g_il + (size_t)bat * S_LEN * DM;

    float acc[2][8][4];
#pragma unroll
    for (int mi = 0; mi < 2; mi++)
#pragma unroll
        for (int ni = 0; ni < 8; ni++)
#pragma unroll
            for (int j = 0; j < 4; j++) acc[mi][ni][j] = 0.f;

    mainloop(sm, Ah, Al, Bh, Bl, bq, bk, tid, wm, wn, lane, acc);

    float* obase = out + (size_t)bat * S_LEN * S_LEN;
#pragma unroll
    for (int mi = 0; mi < 2; mi++) {
#pragma unroll
        for (int ni = 0; ni < 8; ni++) {
            int col = bk + wn * 64 + ni * 8 + 2 * (lane & 3);
#pragma unroll
            for (int h = 0; h < 2; h++) {
                int row = bq + wm * 32 + mi * 16 + (lane >> 2) + h * 8;
                *(float2*)(obase + (size_t)row * S_LEN + col) =
                    make_float2(acc[mi][ni][2 * h + 0], acc[mi][ni][2 * h + 1]);
            }
        }
    }
}

// ---------------------------------------------------------------------------
// Kernel 5: rowwise softmax in place over d_out (16384 rows x 4096)
// ---------------------------------------------------------------------------
__global__ __launch_bounds__(256) void softmax_kernel(float* __restrict__ out) {
    __shared__ float red[8];
    const int t = threadIdx.x, lane = t & 31, warp = t >> 5;
    float* p = out + (size_t)blockIdx.x * S_LEN;

    float4 v[4];
#pragma unroll
    for (int i = 0; i < 4; i++) v[i] = *(const float4*)(p + (i * 256 + t) * 4);

    float mx = -INFINITY;
#pragma unroll
    for (int i = 0; i < 4; i++)
        mx = fmaxf(mx, fmaxf(fmaxf(v[i].x, v[i].y), fmaxf(v[i].z, v[i].w)));
#pragma unroll
    for (int o = 16; o >= 1; o >>= 1)
        mx = fmaxf(mx, __shfl_xor_sync(0xffffffffu, mx, o));
    if (lane == 0) red[warp] = mx;
    __syncthreads();
    float bmx = red[0];
#pragma unroll
    for (int w = 1; w < 8; w++) bmx = fmaxf(bmx, red[w]);
    __syncthreads();

    float sum = 0.f;
#pragma unroll
    for (int i = 0; i < 4; i++) {
        v[i].x = expf(v[i].x - bmx); sum += v[i].x;
        v[i].y = expf(v[i].y - bmx); sum += v[i].y;
        v[i].z = expf(v[i].z - bmx); sum += v[i].z;
        v[i].w = expf(v[i].w - bmx); sum += v[i].w;
    }
#pragma unroll
    for (int o = 16; o >= 1; o >>= 1)
        sum += __shfl_xor_sync(0xffffffffu, sum, o);
    if (lane == 0) red[warp] = sum;
    __syncthreads();
    float bsum = 0.f;
#pragma unroll
    for (int w = 0; w < 8; w++) bsum += red[w];

    float inv = 1.0f / bsum;
#pragma unroll
    for (int i = 0; i < 4; i++) {
        v[i].x *= inv; v[i].y *= inv; v[i].z *= inv; v[i].w *= inv;
        *(float4*)(p + (i * 256 + t) * 4) = v[i];
    }
}

// ---------------------------------------------------------------------------
// Launch
// ---------------------------------------------------------------------------
extern "C" void kernel_launch(void* const* d_in, const int* in_sizes, int n_in,
                              void* d_out, int out_size) {
    (void)in_sizes; (void)n_in; (void)out_size;
    const float* hidden = (const float*)d_in[0];
    const float* pre    = (const float*)d_in[1];
    const float* w1     = (const float*)d_in[2];
    const float* b1     = (const float*)d_in[3];
    const float* w2     = (const float*)d_in[4];
    const float* b2     = (const float*)d_in[5];
    float* out = (float*)d_out;

    cudaFuncSetAttribute(gemm1_kernel,
                         cudaFuncAttributeMaxDynamicSharedMemorySize, SMEM_BYTES);
    cudaFuncSetAttribute(gemm2_kernel,
                         cudaFuncAttributeMaxDynamicSharedMemorySize, SMEM_BYTES);

    split_x_kernel<<<(MTOT * DM) / (256 * 4), 256>>>(hidden, pre);
    split_wT_kernel<<<dim3(DM / 32, DM / 32), 256>>>(w1, w2);
    gemm1_kernel<<<dim3(DM / 128, MTOT / 128, 2), 256, SMEM_BYTES>>>(b1, b2);
    gemm2_kernel<<<dim3(S_LEN / 128, S_LEN / 128, BATCH), 256, SMEM_BYTES>>>(out);
    softmax_kernel<<<MTOT, 256>>>(out);
}